// round 7
// baseline (speedup 1.0000x reference)
#include <cuda_runtime.h>
#include <cuda_bf16.h>
#include <math.h>
#include <float.h>

// Shapes (fixed): B=4, NP=4096, D_FEAT=8, N=16, DM=16, DO=8, NM=64, PNM=64
#define BIGF 99999999.0f

// ---------------- scratch (__device__ globals) ----------------------------
__device__ int   g_idx[4 * 4096 * 16];      // knn indices, ascending-distance order
__device__ float g_zpart[4 * 4096 * 64];    // per-(b,n) z partial sums
__device__ float g_zp2[4 * 64 * 64];        // stage-1 z reduction partials
__device__ float g_zm[4 * 8];               // z @ Wmz + bmz
__device__ float g_zv[4 * 64];              // z @ Wvz + bvz

// ---------------- z-mixing biases -----------------------------------------
__global__ void zmix_kernel(const float* __restrict__ z,
                            const float* __restrict__ Wmz, const float* __restrict__ bmz,
                            const float* __restrict__ Wvz, const float* __restrict__ bvz)
{
    int t = threadIdx.x;
    if (t < 256) {                        // zv: 4 batches x 64
        int b = t >> 6, j = t & 63;
        float s = bvz[j];
        #pragma unroll 8
        for (int p = 0; p < 64; p++) s = fmaf(z[b * 64 + p], Wvz[p * 64 + j], s);
        g_zv[t] = s;
    } else if (t < 288) {                 // zm: 4 batches x 8
        int q = t - 256;
        int b = q >> 3, j = q & 7;
        float s = bmz[j];
        #pragma unroll 8
        for (int p = 0; p < 64; p++) s = fmaf(z[b * 64 + p], Wmz[p * 8 + j], s);
        g_zm[q] = s;
    }
}

// ---------------- kNN helpers ---------------------------------------------
__device__ __forceinline__ void ins8(float key,
    float& s0, float& s1, float& s2, float& s3,
    float& s4, float& s5, float& s6, float& s7)
{
    float tv = key, mn;
    mn = fminf(s0, tv); tv = fmaxf(s0, tv); s0 = mn;
    mn = fminf(s1, tv); tv = fmaxf(s1, tv); s1 = mn;
    mn = fminf(s2, tv); tv = fmaxf(s2, tv); s2 = mn;
    mn = fminf(s3, tv); tv = fmaxf(s3, tv); s3 = mn;
    mn = fminf(s4, tv); tv = fmaxf(s4, tv); s4 = mn;
    mn = fminf(s5, tv); tv = fmaxf(s5, tv); s5 = mn;
    mn = fminf(s6, tv); tv = fmaxf(s6, tv); s6 = mn;
    mn = fminf(s7, tv); tv = fmaxf(s7, tv); s7 = mn;
}

// 19-round tournament: lane r (r<19) ends with the r-th smallest key in surv.
__device__ __forceinline__ float tourney19(int lane,
    float s0, float s1, float s2, float s3,
    float s4, float s5, float s6, float s7)
{
    float head = s0;
    float surv = FLT_MAX;
    #pragma unroll 1
    for (int round = 0; round < 19; round++) {
        float m = head;
        m = fminf(m, __shfl_xor_sync(0xffffffffu, m, 16));
        m = fminf(m, __shfl_xor_sync(0xffffffffu, m, 8));
        m = fminf(m, __shfl_xor_sync(0xffffffffu, m, 4));
        m = fminf(m, __shfl_xor_sync(0xffffffffu, m, 2));
        m = fminf(m, __shfl_xor_sync(0xffffffffu, m, 1));
        if (round == lane) surv = m;
        unsigned bal = __ballot_sync(0xffffffffu, head == m);
        int leader = __ffs(bal) - 1;
        if (lane == leader) {
            s0 = s1; s1 = s2; s2 = s3; s3 = s4;
            s4 = s5; s5 = s6; s6 = s7; s7 = FLT_MAX;
            head = s0;
        }
    }
    return surv;
}

// exact recompute + (dist, idx) rank sort of the 19 survivors, write top-16
__device__ __forceinline__ void finalize19(float surv, int lane, int b, int i,
    float4 a0, float4 a1, float n2i,
    const float4* xs0, const float4* xs1, const float* n2s)
{
    bool valid = (lane < 19) && (surv != FLT_MAX);
    int j = (int)(__float_as_uint(surv) & 0xFFFu);
    unsigned long long pk = 0xffffffffffffffffull;
    if (valid) {
        float4 p0 = xs0[j];
        float4 p1 = xs1[j];
        // reference-exact: serial FMA dot, (n2i+n2j) - 2*dot, sqrt
        float dot = __fmul_rn(a0.x, p0.x);
        dot = __fmaf_rn(a0.y, p0.y, dot);
        dot = __fmaf_rn(a0.z, p0.z, dot);
        dot = __fmaf_rn(a0.w, p0.w, dot);
        dot = __fmaf_rn(a1.x, p1.x, dot);
        dot = __fmaf_rn(a1.y, p1.y, dot);
        dot = __fmaf_rn(a1.z, p1.z, dot);
        dot = __fmaf_rn(a1.w, p1.w, dot);
        float d2 = __fsub_rn(__fadd_rn(n2i, n2s[j]), __fmul_rn(2.0f, dot));
        float dd = sqrtf(fmaxf(d2, 0.0f));
        if (dd == 0.0f || j == i) dd = BIGF;
        pk = ((unsigned long long)__float_as_uint(dd) << 32) | (unsigned)j;
    }
    int rank = 0;
    #pragma unroll
    for (int m = 0; m < 32; m++) {
        unsigned long long o = __shfl_sync(0xffffffffu, pk, m);
        rank += (o < pk) ? 1 : 0;
    }
    if (valid && rank < 16)
        g_idx[(b * 4096 + i) * 16 + rank] = j;
}

// ---------------- kNN: 2 queries per lane, single pass, packed keys -------
// Warp w serves queries i0+w and i0+16+w; each candidate point is loaded
// from smem once and feeds both queries' d2 + insert chains (halves smem
// traffic). key = (d2_bits & ~0xFFF) | j carries the index through plain
// fminf/fmaxf CEs; 19 survivors per query get reference-exact recompute +
// (dist, idx) rank sort.
#define KNN_SMEM (4096*16*2 + 4096*4)   // xs0, xs1, n2s = 147456 B

__global__ __launch_bounds__(512, 1) void knn_kernel(const float* __restrict__ x)
{
    extern __shared__ char smem_raw[];
    float4* xs0 = (float4*)smem_raw;                        // [4096]
    float4* xs1 = (float4*)(smem_raw + 4096 * 16);          // [4096]
    float*  n2s = (float*) (smem_raw + 4096 * 32);          // [4096]

    int b  = blockIdx.x >> 7;
    int i0 = (blockIdx.x & 127) << 5;
    int tid  = threadIdx.x;
    int w    = tid >> 5;               // 0..15
    int lane = tid & 31;

    const float* xb = x + (b << 15);

    // stage points + exact n2 (mul + serial rn adds, matches reference)
    #pragma unroll
    for (int k = 0; k < 8; k++) {
        int p = tid + (k << 9);
        float4 a = *(const float4*)(xb + p * 8);
        float4 c = *(const float4*)(xb + p * 8 + 4);
        xs0[p] = a;
        xs1[p] = c;
        float s = __fmul_rn(a.x, a.x);
        s = __fadd_rn(s, __fmul_rn(a.y, a.y));
        s = __fadd_rn(s, __fmul_rn(a.z, a.z));
        s = __fadd_rn(s, __fmul_rn(a.w, a.w));
        s = __fadd_rn(s, __fmul_rn(c.x, c.x));
        s = __fadd_rn(s, __fmul_rn(c.y, c.y));
        s = __fadd_rn(s, __fmul_rn(c.z, c.z));
        s = __fadd_rn(s, __fmul_rn(c.w, c.w));
        n2s[p] = s;
    }
    __syncthreads();

    int iA = i0 + w;
    int iB = i0 + 16 + w;
    float4 aA0 = xs0[iA], aA1 = xs1[iA];
    float4 aB0 = xs0[iB], aB1 = xs1[iB];
    float n2iA = n2s[iA], n2iB = n2s[iB];

    float A0 = FLT_MAX, A1 = FLT_MAX, A2 = FLT_MAX, A3 = FLT_MAX,
          A4 = FLT_MAX, A5 = FLT_MAX, A6 = FLT_MAX, A7 = FLT_MAX;
    float B0 = FLT_MAX, B1 = FLT_MAX, B2 = FLT_MAX, B3 = FLT_MAX,
          B4 = FLT_MAX, B5 = FLT_MAX, B6 = FLT_MAX, B7 = FLT_MAX;

    {
        int j = lane;
        #pragma unroll 4
        for (int k = 0; k < 128; k++) {
            float4 p0 = xs0[j];
            float4 p1 = xs1[j];
            float n2j = n2s[j];
            // fast d2 (quantization margin absorbs contraction differences)
            float dotA = fmaf(aA0.x, p0.x,
                         fmaf(aA0.y, p0.y,
                         fmaf(aA0.z, p0.z,
                         fmaf(aA0.w, p0.w,
                         fmaf(aA1.x, p1.x,
                         fmaf(aA1.y, p1.y,
                         fmaf(aA1.z, p1.z, aA1.w * p1.w)))))));
            float d2A = fmaf(-2.0f, dotA, n2iA + n2j);
            unsigned kbA = (__float_as_uint(d2A) & 0xFFFFF000u) | (unsigned)j;
            float keyA = (j == iA || d2A <= 0.0f) ? FLT_MAX : __uint_as_float(kbA);
            ins8(keyA, A0, A1, A2, A3, A4, A5, A6, A7);

            float dotB = fmaf(aB0.x, p0.x,
                         fmaf(aB0.y, p0.y,
                         fmaf(aB0.z, p0.z,
                         fmaf(aB0.w, p0.w,
                         fmaf(aB1.x, p1.x,
                         fmaf(aB1.y, p1.y,
                         fmaf(aB1.z, p1.z, aB1.w * p1.w)))))));
            float d2B = fmaf(-2.0f, dotB, n2iB + n2j);
            unsigned kbB = (__float_as_uint(d2B) & 0xFFFFF000u) | (unsigned)j;
            float keyB = (j == iB || d2B <= 0.0f) ? FLT_MAX : __uint_as_float(kbB);
            ins8(keyB, B0, B1, B2, B3, B4, B5, B6, B7);
            j += 32;
        }
    }

    float survA = tourney19(lane, A0, A1, A2, A3, A4, A5, A6, A7);
    float survB = tourney19(lane, B0, B1, B2, B3, B4, B5, B6, B7);

    finalize19(survA, lane, b, iA, aA0, aA1, n2iA, xs0, xs1, n2s);
    finalize19(survB, lane, b, iB, aB0, aB1, n2iB, xs0, xs1, n2s);
}

// ---------------- features + fused matmuls: block per (b,n) ---------------
// DM=16, K = 2*DM = 32 moment columns (cols 0..15 order-2, 16..31 order-3).
// Matmul phase rebalanced: v-matmul spread over all 128 threads (j = t&63,
// r-half = t>>6), halves merged via vpart; m-matmul as 120 (j,r) threads.
__global__ __launch_bounds__(128) void feat_kernel(
    const float* __restrict__ x,
    const float* __restrict__ Wm2, const float* __restrict__ bm2,
    const float* __restrict__ Wm3, const float* __restrict__ bm3,
    const float* __restrict__ Wv2, const float* __restrict__ bv2,
    const float* __restrict__ Wv3, const float* __restrict__ bv3,
    const float* __restrict__ Wmx, const float* __restrict__ bmx,
    const float* __restrict__ Wvx, const float* __restrict__ bvx,
    float* __restrict__ xout)
{
    int b = blockIdx.x >> 12;
    int n = blockIdx.x & 4095;
    int t = threadIdx.x;

    __shared__ __align__(16) float g[16][8];
    __shared__ __align__(16) float msm[15][32];
    __shared__ __align__(16) float vsm[15][32];
    __shared__ float vpart[2][64];
    __shared__ float xr[8][15];

    // gather 16 neighbor feature vectors
    {
        int s = t >> 3, d = t & 7;
        int nb = g_idx[(b * 4096 + n) * 16 + s] & 4095;
        g[s][d] = x[(size_t)(b * 4096 + nb) * 8 + d];
    }

    // feature-phase role
    int c   = t & 31;
    int mat = (t >> 5) & 1;
    int rh  = t >> 6;
    bool o3 = (c >= 16);
    int  k  = o3 ? (c - 16) : c;
    float w0, w1, w2 = 0.f, bb;
    if (!o3) {
        w0 = mat ? Wv2[k]      : Wm2[k];
        w1 = mat ? Wv2[16 + k] : Wm2[16 + k];
        bb = mat ? bv2[k]      : bm2[k];
    } else {
        w0 = mat ? Wv3[k]      : Wm3[k];
        w1 = mat ? Wv3[16 + k] : Wm3[16 + k];
        w2 = mat ? Wv3[32 + k] : Wm3[32 + k];
        bb = mat ? bv3[k]      : bm3[k];
    }
    __syncthreads();

    // r-invariant base: order2 p = g0*w0+b ; order3 p = g0*w0+g1*w1+b
    float p[8];
    #pragma unroll
    for (int d = 0; d < 8; d++) {
        float base = fmaf(g[0][d], w0, bb);
        p[d] = o3 ? fmaf(g[1][d], w1, base) : base;
    }
    float wlast = o3 ? w2 : w1;
    float* smo = mat ? &vsm[0][0] : &msm[0][0];

    int r0 = rh ? 8 : 0;
    int r1 = rh ? 15 : 8;
    for (int r = r0; r < r1; r++) {
        float ssum = 0.f;
        if (o3 && r == 14) {
            // tuple (0,2,3): g0*w0 + g2*w1 + g3*w2 + b
            #pragma unroll
            for (int d = 0; d < 8; d++) {
                float v = fmaf(g[3][d], w2,
                          fmaf(g[2][d], w1,
                          fmaf(g[0][d], w0, bb)));
                ssum += fmaxf(v, 0.f);
            }
        } else {
            int a = o3 ? (r + 2) : (r + 1);
            #pragma unroll
            for (int d = 0; d < 8; d++)
                ssum += fmaxf(fmaf(g[a][d], wlast, p[d]), 0.f);
        }
        smo[r * 32 + c] = ssum * 0.125f;   // mean over d (8)
    }
    __syncthreads();

    // ---- v-matmul: all 128 threads; j = t&63, r-half = t>>6 ----
    {
        int j = t & 63;
        int vh = t >> 6;
        int rbase = vh * 8;
        int nr = vh ? 7 : 8;
        float acc[8];
        #pragma unroll
        for (int rr = 0; rr < 8; rr++) acc[rr] = 0.f;
        #pragma unroll
        for (int k4 = 0; k4 < 32; k4 += 4) {
            float q0 = Wvx[(k4 + 0) * 64 + j];
            float q1 = Wvx[(k4 + 1) * 64 + j];
            float q2 = Wvx[(k4 + 2) * 64 + j];
            float q3 = Wvx[(k4 + 3) * 64 + j];
            #pragma unroll
            for (int rr = 0; rr < 8; rr++) {
                int r = rbase + rr;
                if (r > 14) r = 14;               // vh=1, rr=7: dummy slot
                float4 vv = *(const float4*)&vsm[r][k4];
                acc[rr] = fmaf(vv.x, q0, acc[rr]);
                acc[rr] = fmaf(vv.y, q1, acc[rr]);
                acc[rr] = fmaf(vv.z, q2, acc[rr]);
                acc[rr] = fmaf(vv.w, q3, acc[rr]);
            }
        }
        float bias = bvx[j] + g_zv[b * 64 + j];
        float s = 0.f;
        #pragma unroll
        for (int rr = 0; rr < 8; rr++)
            if (rr < nr) s += fmaxf(acc[rr] + bias, 0.f);
        vpart[vh][j] = s;
    }

    // ---- m-matmul: 120 threads, one (j, r) pair each, K=32 ----
    if (t < 120) {
        int mj = t / 15;
        int mr = t % 15;
        float a = 0.f;
        #pragma unroll
        for (int k4 = 0; k4 < 32; k4 += 4) {
            float4 mv = *(const float4*)&msm[mr][k4];
            a = fmaf(mv.x, Wmx[(k4 + 0) * 8 + mj], a);
            a = fmaf(mv.y, Wmx[(k4 + 1) * 8 + mj], a);
            a = fmaf(mv.z, Wmx[(k4 + 2) * 8 + mj], a);
            a = fmaf(mv.w, Wmx[(k4 + 3) * 8 + mj], a);
        }
        xr[mj][mr] = fmaxf(a + bmx[mj] + g_zm[b * 8 + mj], 0.f);
    }
    __syncthreads();

    if (t < 64)
        g_zpart[(size_t)(b * 4096 + n) * 64 + t] = vpart[0][t] + vpart[1][t];
    if (t < 8) {
        float s = 0.f;
        #pragma unroll
        for (int r = 0; r < 15; r++) s += xr[t][r];
        xout[(size_t)b * 32768 + n * 8 + t] = s * (1.f / 15.f);
    }
}

// ---------------- z reduction, two-stage ----------------------------------
__global__ __launch_bounds__(256) void zred1_kernel()
{
    int b = blockIdx.x >> 6;
    int c = blockIdx.x & 63;
    int t = threadIdx.x;
    int q = t >> 6, j = t & 63;
    const float* zp = g_zpart + ((size_t)(b * 4096 + c * 64) * 64);
    float s = 0.f;
    #pragma unroll 4
    for (int k = q * 16; k < q * 16 + 16; k++) s += zp[k * 64 + j];
    __shared__ float red[256];
    red[t] = s;
    __syncthreads();
    if (t < 64)
        g_zp2[(b * 64 + c) * 64 + t] =
            red[t] + red[t + 64] + red[t + 128] + red[t + 192];
}

__global__ __launch_bounds__(64) void zred2_kernel(float* __restrict__ out)
{
    int b = blockIdx.x;
    int j = threadIdx.x;
    float s = 0.f;
    #pragma unroll 8
    for (int c = 0; c < 64; c++) s += g_zp2[(b * 64 + c) * 64 + j];
    out[131072 + b * 64 + j] = s * (1.f / 61440.f);
}

// ---------------- launch ---------------------------------------------------
extern "C" void kernel_launch(void* const* d_in, const int* in_sizes, int n_in,
                              void* d_out, int out_size)
{
    const float* x   = (const float*)d_in[0];
    const float* z   = (const float*)d_in[1];
    const float* Wm2 = (const float*)d_in[2];
    const float* bm2 = (const float*)d_in[3];
    const float* Wm3 = (const float*)d_in[4];
    const float* bm3 = (const float*)d_in[5];
    const float* Wv2 = (const float*)d_in[6];
    const float* bv2 = (const float*)d_in[7];
    const float* Wv3 = (const float*)d_in[8];
    const float* bv3 = (const float*)d_in[9];
    const float* Wmx = (const float*)d_in[10];
    const float* bmx = (const float*)d_in[11];
    const float* Wvx = (const float*)d_in[12];
    const float* bvx = (const float*)d_in[13];
    const float* Wmz = (const float*)d_in[14];
    const float* bmz = (const float*)d_in[15];
    const float* Wvz = (const float*)d_in[16];
    const float* bvz = (const float*)d_in[17];
    float* out = (float*)d_out;

    cudaFuncSetAttribute(knn_kernel,
                         cudaFuncAttributeMaxDynamicSharedMemorySize, KNN_SMEM);

    zmix_kernel<<<1, 288>>>(z, Wmz, bmz, Wvz, bvz);
    knn_kernel<<<512, 512, KNN_SMEM>>>(x);
    feat_kernel<<<16384, 128>>>(x,
                                Wm2, bm2, Wm3, bm3, Wv2, bv2, Wv3, bv3,
                                Wmx, bmx, Wvx, bvx, out);
    zred1_kernel<<<256, 256>>>();
    zred2_kernel<<<4, 64>>>(out);
}

// round 8
// speedup vs baseline: 1.1809x; 1.1809x over previous
#include <cuda_runtime.h>
#include <cuda_bf16.h>
#include <math.h>
#include <float.h>

// Shapes (fixed): B=4, NP=4096, D_FEAT=8, N=16, DM=16, DO=8, NM=64, PNM=64
#define BIGF 99999999.0f

// ---------------- scratch (__device__ globals) ----------------------------
__device__ int   g_idx[4 * 4096 * 16];      // knn indices, ascending-distance order
__device__ float g_zpart[4 * 4096 * 64];    // per-(b,n) z partial sums
__device__ float g_zp2[4 * 64 * 64];        // stage-1 z reduction partials
__device__ float g_zm[4 * 8];               // z @ Wmz + bmz
__device__ float g_zv[4 * 64];              // z @ Wvz + bvz

// ---------------- z-mixing biases -----------------------------------------
__global__ void zmix_kernel(const float* __restrict__ z,
                            const float* __restrict__ Wmz, const float* __restrict__ bmz,
                            const float* __restrict__ Wvz, const float* __restrict__ bvz)
{
    int t = threadIdx.x;
    if (t < 256) {                        // zv: 4 batches x 64
        int b = t >> 6, j = t & 63;
        float s = bvz[j];
        #pragma unroll 8
        for (int p = 0; p < 64; p++) s = fmaf(z[b * 64 + p], Wvz[p * 64 + j], s);
        g_zv[t] = s;
    } else if (t < 288) {                 // zm: 4 batches x 8
        int q = t - 256;
        int b = q >> 3, j = q & 7;
        float s = bmz[j];
        #pragma unroll 8
        for (int p = 0; p < 64; p++) s = fmaf(z[b * 64 + p], Wmz[p * 8 + j], s);
        g_zm[q] = s;
    }
}

// ---------------- kNN: warp-per-query, single pass, packed keys -----------
// (EXACT R6 version — known 115us / rel_err 8.519306e-6; do not touch.)
// key = (d2_bits & ~0xFFF) | j : positive-float order == (d2 quantized to
// 2^-11 relative, idx) lexicographic, so plain fminf/fmaxf CE carries the
// index for free. Per-lane sorted top-8 over 128 candidates; 19-round warp
// tournament emits the 19 smallest keys (margin 3 over the needed 16 covers
// quantization-bucket collisions); survivors' d2/dist recomputed with the
// reference's exact arithmetic and rank-sorted by exact (dist, idx).
#define KNN_SMEM (4096*16*2 + 4096*4)   // xs0, xs1, n2s = 147456 B

__global__ __launch_bounds__(1024, 1) void knn_kernel(const float* __restrict__ x)
{
    extern __shared__ char smem_raw[];
    float4* xs0 = (float4*)smem_raw;                        // [4096]
    float4* xs1 = (float4*)(smem_raw + 4096 * 16);          // [4096]
    float*  n2s = (float*) (smem_raw + 4096 * 32);          // [4096]

    int b  = blockIdx.x >> 7;
    int i0 = (blockIdx.x & 127) << 5;
    int tid  = threadIdx.x;
    int w    = tid >> 5;
    int lane = tid & 31;

    const float* xb = x + (b << 15);

    // stage points + exact n2 (mul + serial rn adds, matches reference)
    #pragma unroll
    for (int k = 0; k < 4; k++) {
        int p = tid + (k << 10);
        float4 a = *(const float4*)(xb + p * 8);
        float4 c = *(const float4*)(xb + p * 8 + 4);
        xs0[p] = a;
        xs1[p] = c;
        float s = __fmul_rn(a.x, a.x);
        s = __fadd_rn(s, __fmul_rn(a.y, a.y));
        s = __fadd_rn(s, __fmul_rn(a.z, a.z));
        s = __fadd_rn(s, __fmul_rn(a.w, a.w));
        s = __fadd_rn(s, __fmul_rn(c.x, c.x));
        s = __fadd_rn(s, __fmul_rn(c.y, c.y));
        s = __fadd_rn(s, __fmul_rn(c.z, c.z));
        s = __fadd_rn(s, __fmul_rn(c.w, c.w));
        n2s[p] = s;
    }
    __syncthreads();

    int i = i0 + w;                    // this warp's query
    float4 a0 = xs0[i];
    float4 a1 = xs1[i];
    float n2i = n2s[i];

    // ---- single pass: per-lane sorted top-8 of packed keys ----
    float s0 = FLT_MAX, s1 = FLT_MAX, s2 = FLT_MAX, s3 = FLT_MAX,
          s4 = FLT_MAX, s5 = FLT_MAX, s6 = FLT_MAX, s7 = FLT_MAX;
    {
        int j = lane;
        #pragma unroll 4
        for (int k = 0; k < 128; k++) {
            float4 p0 = xs0[j];
            float4 p1 = xs1[j];
            float dot = fmaf(a0.x, p0.x,
                        fmaf(a0.y, p0.y,
                        fmaf(a0.z, p0.z,
                        fmaf(a0.w, p0.w,
                        fmaf(a1.x, p1.x,
                        fmaf(a1.y, p1.y,
                        fmaf(a1.z, p1.z, a1.w * p1.w)))))));
            float d2 = fmaf(-2.0f, dot, n2i + n2s[j]);
            unsigned kb = (__float_as_uint(d2) & 0xFFFFF000u) | (unsigned)j;
            float key = (j == i || d2 <= 0.0f) ? FLT_MAX : __uint_as_float(kb);
            float tv = key, mn;
            mn = fminf(s0, tv); tv = fmaxf(s0, tv); s0 = mn;
            mn = fminf(s1, tv); tv = fmaxf(s1, tv); s1 = mn;
            mn = fminf(s2, tv); tv = fmaxf(s2, tv); s2 = mn;
            mn = fminf(s3, tv); tv = fmaxf(s3, tv); s3 = mn;
            mn = fminf(s4, tv); tv = fmaxf(s4, tv); s4 = mn;
            mn = fminf(s5, tv); tv = fmaxf(s5, tv); s5 = mn;
            mn = fminf(s6, tv); tv = fmaxf(s6, tv); s6 = mn;
            mn = fminf(s7, tv); tv = fmaxf(s7, tv); s7 = mn;
            j += 32;
        }
    }

    // ---- 19-round tournament: lane r keeps the r-th smallest key ----
    float head = s0;
    float surv = FLT_MAX;
    #pragma unroll 1
    for (int round = 0; round < 19; round++) {
        float m = head;
        m = fminf(m, __shfl_xor_sync(0xffffffffu, m, 16));
        m = fminf(m, __shfl_xor_sync(0xffffffffu, m, 8));
        m = fminf(m, __shfl_xor_sync(0xffffffffu, m, 4));
        m = fminf(m, __shfl_xor_sync(0xffffffffu, m, 2));
        m = fminf(m, __shfl_xor_sync(0xffffffffu, m, 1));
        if (round == lane) surv = m;
        unsigned bal = __ballot_sync(0xffffffffu, head == m);
        int leader = __ffs(bal) - 1;
        if (lane == leader) {
            s0 = s1; s1 = s2; s2 = s3; s3 = s4;
            s4 = s5; s5 = s6; s6 = s7; s7 = FLT_MAX;
            head = s0;
        }
    }

    // ---- exact recompute + (dist, idx) rank sort of the 19 survivors ----
    {
        bool valid = (lane < 19) && (surv != FLT_MAX);
        int j = (int)(__float_as_uint(surv) & 0xFFFu);
        unsigned long long pk = 0xffffffffffffffffull;
        if (valid) {
            float4 p0 = xs0[j];
            float4 p1 = xs1[j];
            float dot = __fmul_rn(a0.x, p0.x);
            dot = __fmaf_rn(a0.y, p0.y, dot);
            dot = __fmaf_rn(a0.z, p0.z, dot);
            dot = __fmaf_rn(a0.w, p0.w, dot);
            dot = __fmaf_rn(a1.x, p1.x, dot);
            dot = __fmaf_rn(a1.y, p1.y, dot);
            dot = __fmaf_rn(a1.z, p1.z, dot);
            dot = __fmaf_rn(a1.w, p1.w, dot);
            float d2 = __fsub_rn(__fadd_rn(n2i, n2s[j]), __fmul_rn(2.0f, dot));
            float dd = sqrtf(fmaxf(d2, 0.0f));
            if (dd == 0.0f || j == i) dd = BIGF;
            pk = ((unsigned long long)__float_as_uint(dd) << 32) | (unsigned)j;
        }
        int rank = 0;
        #pragma unroll
        for (int m = 0; m < 32; m++) {
            unsigned long long o = __shfl_sync(0xffffffffu, pk, m);
            rank += (o < pk) ? 1 : 0;
        }
        if (valid && rank < 16)
            g_idx[(b * 4096 + i) * 16 + rank] = j;
    }
}

// ---------------- features + fused matmuls: block per (b,n) ---------------
// DM=16, K = 2*DM = 32 moment columns (cols 0..15 order-2, 16..31 order-3).
// Rebalanced matmul phase with conflict-free layouts:
//  - vsm[15][32]: v-moments, rows read via uniform-address LDS.128 broadcast.
//  - msmT[32][17]: m-moments TRANSPOSED (msmT[c][r]); pad 17 makes both the
//    feature-phase writes (lane stride 17) and m-matmul reads (lane stride 1)
//    bank-conflict-free.
//  - v-matmul across all 128 threads (j = t&63, r-half = t>>6), halves merged
//    via vpart; m-matmul as 120 (j,r) threads, 32 FMA each.
__global__ __launch_bounds__(128) void feat_kernel(
    const float* __restrict__ x,
    const float* __restrict__ Wm2, const float* __restrict__ bm2,
    const float* __restrict__ Wm3, const float* __restrict__ bm3,
    const float* __restrict__ Wv2, const float* __restrict__ bv2,
    const float* __restrict__ Wv3, const float* __restrict__ bv3,
    const float* __restrict__ Wmx, const float* __restrict__ bmx,
    const float* __restrict__ Wvx, const float* __restrict__ bvx,
    float* __restrict__ xout)
{
    int b = blockIdx.x >> 12;
    int n = blockIdx.x & 4095;
    int t = threadIdx.x;

    __shared__ __align__(16) float g[16][8];
    __shared__ __align__(16) float vsm[15][32];
    __shared__ float msmT[32][17];
    __shared__ float vpart[2][64];
    __shared__ float xr[8][15];

    // gather 16 neighbor feature vectors
    {
        int s = t >> 3, d = t & 7;
        int nb = g_idx[(b * 4096 + n) * 16 + s] & 4095;
        g[s][d] = x[(size_t)(b * 4096 + nb) * 8 + d];
    }

    // feature-phase role
    int c   = t & 31;
    int mat = (t >> 5) & 1;
    int rh  = t >> 6;
    bool o3 = (c >= 16);
    int  k  = o3 ? (c - 16) : c;
    float w0, w1, w2 = 0.f, bb;
    if (!o3) {
        w0 = mat ? Wv2[k]      : Wm2[k];
        w1 = mat ? Wv2[16 + k] : Wm2[16 + k];
        bb = mat ? bv2[k]      : bm2[k];
    } else {
        w0 = mat ? Wv3[k]      : Wm3[k];
        w1 = mat ? Wv3[16 + k] : Wm3[16 + k];
        w2 = mat ? Wv3[32 + k] : Wm3[32 + k];
        bb = mat ? bv3[k]      : bm3[k];
    }
    __syncthreads();

    // r-invariant base: order2 p = g0*w0+b ; order3 p = g0*w0+g1*w1+b
    float p[8];
    #pragma unroll
    for (int d = 0; d < 8; d++) {
        float base = fmaf(g[0][d], w0, bb);
        p[d] = o3 ? fmaf(g[1][d], w1, base) : base;
    }
    float wlast = o3 ? w2 : w1;

    int r0 = rh ? 8 : 0;
    int r1 = rh ? 15 : 8;
    for (int r = r0; r < r1; r++) {
        float ssum = 0.f;
        if (o3 && r == 14) {
            // tuple (0,2,3): g0*w0 + g2*w1 + g3*w2 + b
            #pragma unroll
            for (int d = 0; d < 8; d++) {
                float v = fmaf(g[3][d], w2,
                          fmaf(g[2][d], w1,
                          fmaf(g[0][d], w0, bb)));
                ssum += fmaxf(v, 0.f);
            }
        } else {
            int a = o3 ? (r + 2) : (r + 1);
            #pragma unroll
            for (int d = 0; d < 8; d++)
                ssum += fmaxf(fmaf(g[a][d], wlast, p[d]), 0.f);
        }
        ssum *= 0.125f;                    // mean over d (8)
        if (mat) vsm[r][c]  = ssum;
        else     msmT[c][r] = ssum;
    }
    __syncthreads();

    // ---- v-matmul: all 128 threads; j = t&63, r-half = t>>6 ----
    {
        int j = t & 63;
        int vh = t >> 6;
        int rbase = vh * 8;
        int nr = vh ? 7 : 8;
        float acc[8];
        #pragma unroll
        for (int rr = 0; rr < 8; rr++) acc[rr] = 0.f;
        #pragma unroll
        for (int k4 = 0; k4 < 32; k4 += 4) {
            float q0 = Wvx[(k4 + 0) * 64 + j];
            float q1 = Wvx[(k4 + 1) * 64 + j];
            float q2 = Wvx[(k4 + 2) * 64 + j];
            float q3 = Wvx[(k4 + 3) * 64 + j];
            #pragma unroll
            for (int rr = 0; rr < 8; rr++) {
                int r = rbase + rr;
                if (r > 14) r = 14;               // vh=1, rr=7: dummy slot
                float4 vv = *(const float4*)&vsm[r][k4];
                acc[rr] = fmaf(vv.x, q0, acc[rr]);
                acc[rr] = fmaf(vv.y, q1, acc[rr]);
                acc[rr] = fmaf(vv.z, q2, acc[rr]);
                acc[rr] = fmaf(vv.w, q3, acc[rr]);
            }
        }
        float bias = bvx[j] + g_zv[b * 64 + j];
        float s = 0.f;
        #pragma unroll
        for (int rr = 0; rr < 8; rr++)
            if (rr < nr) s += fmaxf(acc[rr] + bias, 0.f);
        vpart[vh][j] = s;
    }

    // ---- m-matmul: 120 threads, one (j, r) pair each, K=32 ----
    if (t < 120) {
        int mj = t / 15;
        int mr = t % 15;
        float a = 0.f;
        #pragma unroll 8
        for (int kk = 0; kk < 32; kk++)
            a = fmaf(msmT[kk][mr], Wmx[kk * 8 + mj], a);
        xr[mj][mr] = fmaxf(a + bmx[mj] + g_zm[b * 8 + mj], 0.f);
    }
    __syncthreads();

    if (t < 64)
        g_zpart[(size_t)(b * 4096 + n) * 64 + t] = vpart[0][t] + vpart[1][t];
    if (t < 8) {
        float s = 0.f;
        #pragma unroll
        for (int r = 0; r < 15; r++) s += xr[t][r];
        xout[(size_t)b * 32768 + n * 8 + t] = s * (1.f / 15.f);
    }
}

// ---------------- z reduction, two-stage ----------------------------------
__global__ __launch_bounds__(256) void zred1_kernel()
{
    int b = blockIdx.x >> 6;
    int c = blockIdx.x & 63;
    int t = threadIdx.x;
    int q = t >> 6, j = t & 63;
    const float* zp = g_zpart + ((size_t)(b * 4096 + c * 64) * 64);
    float s = 0.f;
    #pragma unroll 4
    for (int k = q * 16; k < q * 16 + 16; k++) s += zp[k * 64 + j];
    __shared__ float red[256];
    red[t] = s;
    __syncthreads();
    if (t < 64)
        g_zp2[(b * 64 + c) * 64 + t] =
            red[t] + red[t + 64] + red[t + 128] + red[t + 192];
}

__global__ __launch_bounds__(64) void zred2_kernel(float* __restrict__ out)
{
    int b = blockIdx.x;
    int j = threadIdx.x;
    float s = 0.f;
    #pragma unroll 8
    for (int c = 0; c < 64; c++) s += g_zp2[(b * 64 + c) * 64 + j];
    out[131072 + b * 64 + j] = s * (1.f / 61440.f);
}

// ---------------- launch ---------------------------------------------------
extern "C" void kernel_launch(void* const* d_in, const int* in_sizes, int n_in,
                              void* d_out, int out_size)
{
    const float* x   = (const float*)d_in[0];
    const float* z   = (const float*)d_in[1];
    const float* Wm2 = (const float*)d_in[2];
    const float* bm2 = (const float*)d_in[3];
    const float* Wm3 = (const float*)d_in[4];
    const float* bm3 = (const float*)d_in[5];
    const float* Wv2 = (const float*)d_in[6];
    const float* bv2 = (const float*)d_in[7];
    const float* Wv3 = (const float*)d_in[8];
    const float* bv3 = (const float*)d_in[9];
    const float* Wmx = (const float*)d_in[10];
    const float* bmx = (const float*)d_in[11];
    const float* Wvx = (const float*)d_in[12];
    const float* bvx = (const float*)d_in[13];
    const float* Wmz = (const float*)d_in[14];
    const float* bmz = (const float*)d_in[15];
    const float* Wvz = (const float*)d_in[16];
    const float* bvz = (const float*)d_in[17];
    float* out = (float*)d_out;

    cudaFuncSetAttribute(knn_kernel,
                         cudaFuncAttributeMaxDynamicSharedMemorySize, KNN_SMEM);

    zmix_kernel<<<1, 288>>>(z, Wmz, bmz, Wvz, bvz);
    knn_kernel<<<512, 1024, KNN_SMEM>>>(x);
    feat_kernel<<<16384, 128>>>(x,
                                Wm2, bm2, Wm3, bm3, Wv2, bv2, Wv3, bv3,
                                Wmx, bmx, Wvx, bvx, out);
    zred1_kernel<<<256, 256>>>();
    zred2_kernel<<<4, 64>>>(out);
}

// round 9
// speedup vs baseline: 1.2076x; 1.0227x over previous
#include <cuda_runtime.h>
#include <cuda_bf16.h>
#include <math.h>
#include <float.h>

// Shapes (fixed): B=4, NP=4096, D_FEAT=8, N=16, DM=16, DO=8, NM=64, PNM=64
#define BIGF 99999999.0f

// ---------------- scratch (__device__ globals) ----------------------------
__device__ int   g_idx[4 * 4096 * 16];      // knn indices, ascending-distance order
__device__ float g_zpart[4 * 4096 * 64];    // per-(b,n) z partial sums
__device__ float g_zp2[4 * 64 * 64];        // stage-1 z reduction partials
__device__ float g_zm[4 * 8];               // z @ Wmz + bmz
__device__ float g_zv[4 * 64];              // z @ Wvz + bvz

// ---------------- z-mixing biases -----------------------------------------
__global__ void zmix_kernel(const float* __restrict__ z,
                            const float* __restrict__ Wmz, const float* __restrict__ bmz,
                            const float* __restrict__ Wvz, const float* __restrict__ bvz)
{
    int t = threadIdx.x;
    if (t < 256) {                        // zv: 4 batches x 64
        int b = t >> 6, j = t & 63;
        float s = bvz[j];
        #pragma unroll 8
        for (int p = 0; p < 64; p++) s = fmaf(z[b * 64 + p], Wvz[p * 64 + j], s);
        g_zv[t] = s;
    } else if (t < 288) {                 // zm: 4 batches x 8
        int q = t - 256;
        int b = q >> 3, j = q & 7;
        float s = bmz[j];
        #pragma unroll 8
        for (int p = 0; p < 64; p++) s = fmaf(z[b * 64 + p], Wmz[p * 8 + j], s);
        g_zm[q] = s;
    }
}

// ---------------- kNN helpers ---------------------------------------------
__device__ __forceinline__ void ins8(float key,
    float& s0, float& s1, float& s2, float& s3,
    float& s4, float& s5, float& s6, float& s7)
{
    float tv = key, mn;
    mn = fminf(s0, tv); tv = fmaxf(s0, tv); s0 = mn;
    mn = fminf(s1, tv); tv = fmaxf(s1, tv); s1 = mn;
    mn = fminf(s2, tv); tv = fmaxf(s2, tv); s2 = mn;
    mn = fminf(s3, tv); tv = fmaxf(s3, tv); s3 = mn;
    mn = fminf(s4, tv); tv = fmaxf(s4, tv); s4 = mn;
    mn = fminf(s5, tv); tv = fmaxf(s5, tv); s5 = mn;
    mn = fminf(s6, tv); tv = fmaxf(s6, tv); s6 = mn;
    mn = fminf(s7, tv); tv = fmaxf(s7, tv); s7 = mn;
}

// 19-round tournament: lane r (r<19) ends with the r-th smallest key in surv.
__device__ __forceinline__ float tourney19(int lane,
    float s0, float s1, float s2, float s3,
    float s4, float s5, float s6, float s7)
{
    float head = s0;
    float surv = FLT_MAX;
    #pragma unroll 1
    for (int round = 0; round < 19; round++) {
        float m = head;
        m = fminf(m, __shfl_xor_sync(0xffffffffu, m, 16));
        m = fminf(m, __shfl_xor_sync(0xffffffffu, m, 8));
        m = fminf(m, __shfl_xor_sync(0xffffffffu, m, 4));
        m = fminf(m, __shfl_xor_sync(0xffffffffu, m, 2));
        m = fminf(m, __shfl_xor_sync(0xffffffffu, m, 1));
        if (round == lane) surv = m;
        unsigned bal = __ballot_sync(0xffffffffu, head == m);
        int leader = __ffs(bal) - 1;
        if (lane == leader) {
            s0 = s1; s1 = s2; s2 = s3; s3 = s4;
            s4 = s5; s5 = s6; s6 = s7; s7 = FLT_MAX;
            head = s0;
        }
    }
    return surv;
}

// exact recompute + (dist, idx) rank sort of the 19 survivors, write top-16
__device__ __forceinline__ void finalize19(float surv, int lane, int b, int i,
    const float4* xs0, const float4* xs1, const float* n2s)
{
    float4 a0 = xs0[i], a1 = xs1[i];
    float n2i = n2s[i];
    bool valid = (lane < 19) && (surv != FLT_MAX);
    int j = (int)(__float_as_uint(surv) & 0xFFFu);
    unsigned long long pk = 0xffffffffffffffffull;
    if (valid) {
        float4 p0 = xs0[j];
        float4 p1 = xs1[j];
        // reference-exact: serial FMA dot, (n2i+n2j) - 2*dot, sqrt
        float dot = __fmul_rn(a0.x, p0.x);
        dot = __fmaf_rn(a0.y, p0.y, dot);
        dot = __fmaf_rn(a0.z, p0.z, dot);
        dot = __fmaf_rn(a0.w, p0.w, dot);
        dot = __fmaf_rn(a1.x, p1.x, dot);
        dot = __fmaf_rn(a1.y, p1.y, dot);
        dot = __fmaf_rn(a1.z, p1.z, dot);
        dot = __fmaf_rn(a1.w, p1.w, dot);
        float d2 = __fsub_rn(__fadd_rn(n2i, n2s[j]), __fmul_rn(2.0f, dot));
        float dd = sqrtf(fmaxf(d2, 0.0f));
        if (dd == 0.0f || j == i) dd = BIGF;
        pk = ((unsigned long long)__float_as_uint(dd) << 32) | (unsigned)j;
    }
    int rank = 0;
    #pragma unroll
    for (int m = 0; m < 32; m++) {
        unsigned long long o = __shfl_sync(0xffffffffu, pk, m);
        rank += (o < pk) ? 1 : 0;
    }
    if (valid && rank < 16)
        g_idx[(b * 4096 + i) * 16 + rank] = j;
}

// ---------------- kNN: 1024 thr, 2 queries/warp, packed keys --------------
// 256 blocks of 64 queries. Warp w serves queries i0+w and i0+32+w: every
// candidate point is loaded from smem once and feeds both queries (halves
// smem traffic vs R6) while keeping 32 resident warps/SM (R7's occupancy
// mistake fixed). key = (d2_bits & ~0xFFF) | j carries the index through
// plain fminf/fmaxf CEs; 19 survivors/query -> reference-exact recompute +
// (dist, idx) rank sort.
#define KNN_SMEM (4096*16*2 + 4096*4)   // xs0, xs1, n2s = 147456 B

__global__ __launch_bounds__(1024, 1) void knn_kernel(const float* __restrict__ x)
{
    extern __shared__ char smem_raw[];
    float4* xs0 = (float4*)smem_raw;                        // [4096]
    float4* xs1 = (float4*)(smem_raw + 4096 * 16);          // [4096]
    float*  n2s = (float*) (smem_raw + 4096 * 32);          // [4096]

    int tid  = threadIdx.x;
    int lane = tid & 31;

    const float* xb = x + ((blockIdx.x >> 6) << 15);

    // stage points + exact n2 (mul + serial rn adds, matches reference)
    #pragma unroll
    for (int k = 0; k < 4; k++) {
        int p = tid + (k << 10);
        float4 a = *(const float4*)(xb + p * 8);
        float4 c = *(const float4*)(xb + p * 8 + 4);
        xs0[p] = a;
        xs1[p] = c;
        float s = __fmul_rn(a.x, a.x);
        s = __fadd_rn(s, __fmul_rn(a.y, a.y));
        s = __fadd_rn(s, __fmul_rn(a.z, a.z));
        s = __fadd_rn(s, __fmul_rn(a.w, a.w));
        s = __fadd_rn(s, __fmul_rn(c.x, c.x));
        s = __fadd_rn(s, __fmul_rn(c.y, c.y));
        s = __fadd_rn(s, __fmul_rn(c.z, c.z));
        s = __fadd_rn(s, __fmul_rn(c.w, c.w));
        n2s[p] = s;
    }
    __syncthreads();

    int iA = ((blockIdx.x & 63) << 6) + (tid >> 5);        // i0 + w
    int iB = iA + 32;
    float4 aA0 = xs0[iA], aA1 = xs1[iA];
    float4 aB0 = xs0[iB], aB1 = xs1[iB];
    float n2iA = n2s[iA], n2iB = n2s[iB];

    float A0 = FLT_MAX, A1 = FLT_MAX, A2 = FLT_MAX, A3 = FLT_MAX,
          A4 = FLT_MAX, A5 = FLT_MAX, A6 = FLT_MAX, A7 = FLT_MAX;
    float B0 = FLT_MAX, B1 = FLT_MAX, B2 = FLT_MAX, B3 = FLT_MAX,
          B4 = FLT_MAX, B5 = FLT_MAX, B6 = FLT_MAX, B7 = FLT_MAX;

    {
        int j = lane;
        #pragma unroll 4
        for (int k = 0; k < 128; k++) {
            float4 p0 = xs0[j];
            float4 p1 = xs1[j];
            float n2j = n2s[j];
            // fast d2 (2^-11 quantization margin absorbs contraction diffs)
            float dotA = fmaf(aA0.x, p0.x,
                         fmaf(aA0.y, p0.y,
                         fmaf(aA0.z, p0.z,
                         fmaf(aA0.w, p0.w,
                         fmaf(aA1.x, p1.x,
                         fmaf(aA1.y, p1.y,
                         fmaf(aA1.z, p1.z, aA1.w * p1.w)))))));
            float d2A = fmaf(-2.0f, dotA, n2iA + n2j);
            unsigned kbA = (__float_as_uint(d2A) & 0xFFFFF000u) | (unsigned)j;
            float keyA = (j == iA || d2A <= 0.0f) ? FLT_MAX : __uint_as_float(kbA);
            ins8(keyA, A0, A1, A2, A3, A4, A5, A6, A7);

            float dotB = fmaf(aB0.x, p0.x,
                         fmaf(aB0.y, p0.y,
                         fmaf(aB0.z, p0.z,
                         fmaf(aB0.w, p0.w,
                         fmaf(aB1.x, p1.x,
                         fmaf(aB1.y, p1.y,
                         fmaf(aB1.z, p1.z, aB1.w * p1.w)))))));
            float d2B = fmaf(-2.0f, dotB, n2iB + n2j);
            unsigned kbB = (__float_as_uint(d2B) & 0xFFFFF000u) | (unsigned)j;
            float keyB = (j == iB || d2B <= 0.0f) ? FLT_MAX : __uint_as_float(kbB);
            ins8(keyB, B0, B1, B2, B3, B4, B5, B6, B7);
            j += 32;
        }
    }

    float survA = tourney19(lane, A0, A1, A2, A3, A4, A5, A6, A7);
    float survB = tourney19(lane, B0, B1, B2, B3, B4, B5, B6, B7);

    int b = blockIdx.x >> 6;
    finalize19(survA, lane, b, iA, xs0, xs1, n2s);
    finalize19(survB, lane, b, iB, xs0, xs1, n2s);
}

// ---------------- features + fused matmuls: block per (b,n) ---------------
// (EXACT R6 version — known-good 76us.)
// DM=16, K = 2*DM = 32 moment columns (cols 0..15 order-2, 16..31 order-3).
__global__ __launch_bounds__(128) void feat_kernel(
    const float* __restrict__ x,
    const float* __restrict__ Wm2, const float* __restrict__ bm2,
    const float* __restrict__ Wm3, const float* __restrict__ bm3,
    const float* __restrict__ Wv2, const float* __restrict__ bv2,
    const float* __restrict__ Wv3, const float* __restrict__ bv3,
    const float* __restrict__ Wmx, const float* __restrict__ bmx,
    const float* __restrict__ Wvx, const float* __restrict__ bvx,
    float* __restrict__ xout)
{
    int b = blockIdx.x >> 12;
    int n = blockIdx.x & 4095;
    int t = threadIdx.x;

    __shared__ __align__(16) float g[16][8];
    __shared__ __align__(16) float msm[15][32];
    __shared__ __align__(16) float vsm[15][32];
    __shared__ float mpart[8][8][15];   // [j][slice][r]
    __shared__ float xr[8][15];

    // gather 16 neighbor feature vectors
    {
        int s = t >> 3, d = t & 7;
        int nb = g_idx[(b * 4096 + n) * 16 + s] & 4095;
        g[s][d] = x[(size_t)(b * 4096 + nb) * 8 + d];
    }

    // feature-phase role
    int c   = t & 31;
    int mat = (t >> 5) & 1;
    int rh  = t >> 6;
    bool o3 = (c >= 16);
    int  k  = o3 ? (c - 16) : c;
    float w0, w1, w2 = 0.f, bb;
    if (!o3) {
        w0 = mat ? Wv2[k]      : Wm2[k];
        w1 = mat ? Wv2[16 + k] : Wm2[16 + k];
        bb = mat ? bv2[k]      : bm2[k];
    } else {
        w0 = mat ? Wv3[k]      : Wm3[k];
        w1 = mat ? Wv3[16 + k] : Wm3[16 + k];
        w2 = mat ? Wv3[32 + k] : Wm3[32 + k];
        bb = mat ? bv3[k]      : bm3[k];
    }
    __syncthreads();

    // r-invariant base: order2 p = g0*w0+b ; order3 p = g0*w0+g1*w1+b
    float p[8];
    #pragma unroll
    for (int d = 0; d < 8; d++) {
        float base = fmaf(g[0][d], w0, bb);
        p[d] = o3 ? fmaf(g[1][d], w1, base) : base;
    }
    float wlast = o3 ? w2 : w1;
    float* smo = mat ? &vsm[0][0] : &msm[0][0];

    int r0 = rh ? 8 : 0;
    int r1 = rh ? 15 : 8;
    for (int r = r0; r < r1; r++) {
        float ssum = 0.f;
        if (o3 && r == 14) {
            // tuple (0,2,3): g0*w0 + g2*w1 + g3*w2 + b
            #pragma unroll
            for (int d = 0; d < 8; d++) {
                float v = fmaf(g[3][d], w2,
                          fmaf(g[2][d], w1,
                          fmaf(g[0][d], w0, bb)));
                ssum += fmaxf(v, 0.f);
            }
        } else {
            int a = o3 ? (r + 2) : (r + 1);
            #pragma unroll
            for (int d = 0; d < 8; d++)
                ssum += fmaxf(fmaf(g[a][d], wlast, p[d]), 0.f);
        }
        smo[r * 32 + c] = ssum * 0.125f;   // mean over d (8)
    }
    __syncthreads();

    if (t < 64) {
        // v-matmul: output j=t, K=32, 15 tuples
        float acc[15];
        #pragma unroll
        for (int r = 0; r < 15; r++) acc[r] = 0.f;
        #pragma unroll
        for (int k4 = 0; k4 < 32; k4 += 4) {
            float q0 = Wvx[(k4 + 0) * 64 + t];
            float q1 = Wvx[(k4 + 1) * 64 + t];
            float q2 = Wvx[(k4 + 2) * 64 + t];
            float q3 = Wvx[(k4 + 3) * 64 + t];
            #pragma unroll
            for (int r = 0; r < 15; r++) {
                float4 vv = *(const float4*)&vsm[r][k4];
                acc[r] = fmaf(vv.x, q0, acc[r]);
                acc[r] = fmaf(vv.y, q1, acc[r]);
                acc[r] = fmaf(vv.z, q2, acc[r]);
                acc[r] = fmaf(vv.w, q3, acc[r]);
            }
        }
        float bias = bvx[t] + g_zv[b * 64 + t];
        float s = 0.f;
        #pragma unroll
        for (int r = 0; r < 15; r++) s += fmaxf(acc[r] + bias, 0.f);
        g_zpart[(size_t)(b * 4096 + n) * 64 + t] = s;
    } else {
        // m-matmul: 8 outputs x 8 k-slices of 4
        int q = t - 64;
        int j = q >> 3;
        int sl = q & 7;
        int k0 = sl * 4;
        float q0 = Wmx[(k0 + 0) * 8 + j];
        float q1 = Wmx[(k0 + 1) * 8 + j];
        float q2 = Wmx[(k0 + 2) * 8 + j];
        float q3 = Wmx[(k0 + 3) * 8 + j];
        #pragma unroll
        for (int r = 0; r < 15; r++) {
            float4 mv = *(const float4*)&msm[r][k0];
            float a = mv.x * q0;
            a = fmaf(mv.y, q1, a);
            a = fmaf(mv.z, q2, a);
            a = fmaf(mv.w, q3, a);
            mpart[j][sl][r] = a;
        }
    }
    __syncthreads();

    if (t < 120) {
        int j = t / 15, r = t % 15;
        float s = 0.f;
        #pragma unroll
        for (int sl = 0; sl < 8; sl++) s += mpart[j][sl][r];
        xr[j][r] = fmaxf(s + bmx[j] + g_zm[b * 8 + j], 0.f);
    }
    __syncthreads();
    if (t < 8) {
        float s = 0.f;
        #pragma unroll
        for (int r = 0; r < 15; r++) s += xr[t][r];
        xout[(size_t)b * 32768 + n * 8 + t] = s * (1.f / 15.f);
    }
}

// ---------------- z reduction, two-stage ----------------------------------
__global__ __launch_bounds__(256) void zred1_kernel()
{
    int b = blockIdx.x >> 6;
    int c = blockIdx.x & 63;
    int t = threadIdx.x;
    int q = t >> 6, j = t & 63;
    const float* zp = g_zpart + ((size_t)(b * 4096 + c * 64) * 64);
    float s = 0.f;
    #pragma unroll 4
    for (int k = q * 16; k < q * 16 + 16; k++) s += zp[k * 64 + j];
    __shared__ float red[256];
    red[t] = s;
    __syncthreads();
    if (t < 64)
        g_zp2[(b * 64 + c) * 64 + t] =
            red[t] + red[t + 64] + red[t + 128] + red[t + 192];
}

__global__ __launch_bounds__(64) void zred2_kernel(float* __restrict__ out)
{
    int b = blockIdx.x;
    int j = threadIdx.x;
    float s = 0.f;
    #pragma unroll 8
    for (int c = 0; c < 64; c++) s += g_zp2[(b * 64 + c) * 64 + j];
    out[131072 + b * 64 + j] = s * (1.f / 61440.f);
}

// ---------------- launch ---------------------------------------------------
extern "C" void kernel_launch(void* const* d_in, const int* in_sizes, int n_in,
                              void* d_out, int out_size)
{
    const float* x   = (const float*)d_in[0];
    const float* z   = (const float*)d_in[1];
    const float* Wm2 = (const float*)d_in[2];
    const float* bm2 = (const float*)d_in[3];
    const float* Wm3 = (const float*)d_in[4];
    const float* bm3 = (const float*)d_in[5];
    const float* Wv2 = (const float*)d_in[6];
    const float* bv2 = (const float*)d_in[7];
    const float* Wv3 = (const float*)d_in[8];
    const float* bv3 = (const float*)d_in[9];
    const float* Wmx = (const float*)d_in[10];
    const float* bmx = (const float*)d_in[11];
    const float* Wvx = (const float*)d_in[12];
    const float* bvx = (const float*)d_in[13];
    const float* Wmz = (const float*)d_in[14];
    const float* bmz = (const float*)d_in[15];
    const float* Wvz = (const float*)d_in[16];
    const float* bvz = (const float*)d_in[17];
    float* out = (float*)d_out;

    cudaFuncSetAttribute(knn_kernel,
                         cudaFuncAttributeMaxDynamicSharedMemorySize, KNN_SMEM);

    zmix_kernel<<<1, 288>>>(z, Wmz, bmz, Wvz, bvz);
    knn_kernel<<<256, 1024, KNN_SMEM>>>(x);
    feat_kernel<<<16384, 128>>>(x,
                                Wm2, bm2, Wm3, bm3, Wv2, bv2, Wv3, bv3,
                                Wmx, bmx, Wvx, bvx, out);
    zred1_kernel<<<256, 256>>>();
    zred2_kernel<<<4, 64>>>(out);
}